// round 2
// baseline (speedup 1.0000x reference)
#include <cuda_runtime.h>
#include <cuda_bf16.h>

// Problem shape (fixed by the dataset)
#define HH 64
#define WW 128
#define HW (HH * WW)     // 8192 points per image
#define NPAIR 8          // B*S = 2*4
#define SDIM 4
#define BDIM 2

#define NT 128           // threads per NN block
#define QPT 4            // queries per thread
#define QBLK (NT * QPT)  // 512 queries per block
#define TILE 128         // target points per smem tile (one load per thread)

// Scratch (device globals; no allocations allowed)
// g_pts[side][variant][pair][idx] : side 0 = output pts (from rv), side 1 = target pts
// variant 0 = (x, y, z, ||p||^2)       -- used as queries
// variant 1 = (-2x, -2y, -2z, ||p||^2) -- used as NN targets (folds the -2 into FMAs)
__device__ float4 g_pts[2][2][NPAIR][HW];
__device__ int    g_cnt[2][NPAIR];
__device__ float  g_sum[2][NPAIR];

__global__ void init_kernel() {
    int t = threadIdx.x;
    if (t < 16) ((int*)g_cnt)[t] = 0;
    else if (t < 32) ((float*)g_sum)[t - 16] = 0.0f;
}

__device__ __forceinline__ void compact_push(int side, int pair, bool valid,
                                             float x, float y, float z) {
    unsigned m = __ballot_sync(0xffffffffu, valid);
    int lane = threadIdx.x & 31;
    int leader = __ffs(m) - 1;
    int cnt = __popc(m);
    int base = 0;
    if (cnt > 0) {
        if (lane == leader) base = atomicAdd(&g_cnt[side][pair], cnt);
        base = __shfl_sync(0xffffffffu, base, leader);
    }
    if (valid) {
        int pos = base + __popc(m & ((1u << lane) - 1u));
        float n = x * x + y * y + z * z;
        g_pts[side][0][pair][pos] = make_float4(x, y, z, n);
        g_pts[side][1][pair][pos] = make_float4(-2.0f * x, -2.0f * y, -2.0f * z, n);
    }
}

__global__ void prep_kernel(const float* __restrict__ rv,
                            const float* __restrict__ tgt) {
    const int pair = blockIdx.y;
    const int i = blockIdx.x * blockDim.x + threadIdx.x;   // 0..8191
    const int h = i / WW;
    const int w = i % WW;

    const float FOV_DOWN = -0.4363323129985824f;   // -25 deg
    const float FOV      = 0.4886921905584123f;    // 28 deg span
    const float PI_F     = 3.14159265358979323846f;

    float pitch = (1.0f - (h + 0.5f) / (float)HH) * FOV + FOV_DOWN;
    float yaw   = -(((w + 0.5f) / (float)WW) * 2.0f - 1.0f) * PI_F;
    float cp = cosf(pitch), sp = sinf(pitch);
    float cy = cosf(yaw),  sy = sinf(yaw);

    // side 0: back-projected rv points
    float r = rv[pair * HW + i];
    float x = r * cp * cy;
    float y = r * cp * sy;
    float z = r * sp;
    compact_push(0, pair, r > 0.0f, x, y, z);

    // side 1: target points, channels 1..3; mask from channel 0
    const float* tp = tgt + (size_t)pair * 4 * HW + i;
    float t0 = tp[0];
    float tx = tp[HW];
    float ty = tp[2 * HW];
    float tz = tp[3 * HW];
    compact_push(1, pair, t0 > 0.0f, tx, ty, tz);
}

__global__ void nn_kernel() {
    const int dir  = blockIdx.z;        // 0: queries = output pts; 1: queries = target pts
    const int pair = blockIdx.y;
    const int nq = g_cnt[dir][pair];
    const int nt = g_cnt[1 - dir][pair];
    const int qbase = blockIdx.x * QBLK;
    if (qbase >= nq) return;

    const float4* __restrict__ q  = g_pts[dir][0][pair];
    const float4* __restrict__ tg = g_pts[1 - dir][1][pair];

    __shared__ float4 tile[TILE];
    const int tid = threadIdx.x;

    float4 qr[QPT];
    bool   qv[QPT];
#pragma unroll
    for (int k = 0; k < QPT; k++) {
        int idx = qbase + k * NT + tid;
        qv[k] = idx < nq;
        qr[k] = qv[k] ? q[idx] : make_float4(0.f, 0.f, 0.f, 0.f);
    }

    // two min accumulators per query to break the FMNMX dependency chain
    float mn[QPT][2];
#pragma unroll
    for (int k = 0; k < QPT; k++) { mn[k][0] = 3e38f; mn[k][1] = 3e38f; }

    for (int j0 = 0; j0 < nt; j0 += TILE) {
        __syncthreads();
        int j = j0 + tid;
        tile[tid] = (j < nt) ? tg[j] : make_float4(0.f, 0.f, 0.f, 3e38f);
        __syncthreads();
#pragma unroll 4
        for (int jj = 0; jj < TILE; jj += 2) {
            float4 t0 = tile[jj];
            float4 t1 = tile[jj + 1];
#pragma unroll
            for (int k = 0; k < QPT; k++) {
                // v = ||t||^2 - 2*q.t  (query norm added after the min)
                mn[k][0] = fminf(mn[k][0],
                    fmaf(qr[k].x, t0.x, fmaf(qr[k].y, t0.y, fmaf(qr[k].z, t0.z, t0.w))));
                mn[k][1] = fminf(mn[k][1],
                    fmaf(qr[k].x, t1.x, fmaf(qr[k].y, t1.y, fmaf(qr[k].z, t1.z, t1.w))));
            }
        }
    }

    float local = 0.0f;
#pragma unroll
    for (int k = 0; k < QPT; k++)
        if (qv[k]) local += qr[k].w + fminf(mn[k][0], mn[k][1]);

    // block reduction
#pragma unroll
    for (int o = 16; o; o >>= 1) local += __shfl_down_sync(0xffffffffu, local, o);
    __shared__ float wsum[NT / 32];
    if ((tid & 31) == 0) wsum[tid >> 5] = local;
    __syncthreads();
    if (tid < NT / 32) {
        float s = wsum[tid];
#pragma unroll
        for (int o = (NT / 64); o; o >>= 1) s += __shfl_down_sync(0xfu, s, o);
        if (tid == 0) atomicAdd(&g_sum[dir][pair], s);
    }
}

__global__ void final_kernel(float* __restrict__ out) {
    if (threadIdx.x == 0) {
        float cham[NPAIR];
#pragma unroll
        for (int p = 0; p < NPAIR; p++) {
            float c0 = (float)g_cnt[0][p]; if (c0 < 1.0f) c0 = 1.0f;
            float c1 = (float)g_cnt[1][p]; if (c1 < 1.0f) c1 = 1.0f;
            cham[p] = g_sum[0][p] / c0 + g_sum[1][p] / c1;
        }
        // tensor[s][b] = cham[b*SDIM + s]; per_step[s] = mean over b
#pragma unroll
        for (int s = 0; s < SDIM; s++) {
            float acc = 0.0f;
#pragma unroll
            for (int b = 0; b < BDIM; b++) {
                float c = cham[b * SDIM + s];
                out[SDIM + s * BDIM + b] = c;
                acc += c;
            }
            out[s] = acc / (float)BDIM;
        }
    }
}

extern "C" void kernel_launch(void* const* d_in, const int* in_sizes, int n_in,
                              void* d_out, int out_size) {
    const float* rv  = (const float*)d_in[0];
    const float* tgt = (const float*)d_in[1];
    // d_in[2] (mos_label) and d_in[3] (n_samples) are unused per the reference.

    init_kernel<<<1, 32>>>();
    prep_kernel<<<dim3(HW / 256, NPAIR), 256>>>(rv, tgt);
    nn_kernel<<<dim3(HW / QBLK, NPAIR, 2), NT>>>();
    final_kernel<<<1, 32>>>((float*)d_out);
}

// round 3
// speedup vs baseline: 1.4496x; 1.4496x over previous
#include <cuda_runtime.h>
#include <cuda_bf16.h>

// Problem shape (fixed by the dataset)
#define HH 64
#define WW 128
#define HW (HH * WW)     // 8192 points per image
#define NPAIR 8          // B*S = 2*4
#define SDIM 4
#define BDIM 2

#define GX   9           // query blocks per (pair,dir): 9*8*2 = 144 CTAs = 1 wave
#define NT   256         // threads per NN block (2 warps per SMSP)
#define QPT  2           // queries per thread
#define QBLK (NT * QPT)  // 512 queries per block
#define TILE 512         // targets per smem tile
#define NGRP (TILE / 2)  // packed target-pair groups per tile

// Scratch (device globals; zero-initialized at module load, re-zeroed by the
// fused finalizer each call -> every kernel_launch call sees the same state).
// g_pts[side][variant][pair][idx]: side 0 = rv back-projection, side 1 = target
// variant 0 = (x, y, z, ||p||^2)        -- queries
// variant 1 = (-2x, -2y, -2z, ||p||^2)  -- NN targets (-2 folded into FMAs)
__device__ float4 g_pts[2][2][NPAIR][HW];
__device__ int    g_cnt[2][NPAIR];
__device__ float  g_sum[2][NPAIR];
__device__ int    g_done;

// ---------- packed f32x2 helpers ----------
__device__ __forceinline__ unsigned long long splat2(float v) {
    unsigned long long r;
    asm("mov.b64 %0, {%1, %1};" : "=l"(r) : "f"(v));
    return r;
}
__device__ __forceinline__ unsigned long long fma2(unsigned long long a,
                                                   unsigned long long b,
                                                   unsigned long long c) {
    unsigned long long d;
    asm("fma.rn.f32x2 %0, %1, %2, %3;" : "=l"(d) : "l"(a), "l"(b), "l"(c));
    return d;
}
__device__ __forceinline__ float2 unpack2(unsigned long long v) {
    float2 r;
    asm("mov.b64 {%0, %1}, %2;" : "=f"(r.x), "=f"(r.y) : "l"(v));
    return r;
}

// ---------- prep: back-project + warp-aggregated stream compaction ----------
__device__ __forceinline__ void compact_push(int side, int pair, bool valid,
                                             float x, float y, float z) {
    unsigned m = __ballot_sync(0xffffffffu, valid);
    int lane = threadIdx.x & 31;
    int leader = __ffs(m) - 1;
    int cnt = __popc(m);
    int base = 0;
    if (cnt > 0) {
        if (lane == leader) base = atomicAdd(&g_cnt[side][pair], cnt);
        base = __shfl_sync(0xffffffffu, base, leader);
    }
    if (valid) {
        int pos = base + __popc(m & ((1u << lane) - 1u));
        float n = x * x + y * y + z * z;
        g_pts[side][0][pair][pos] = make_float4(x, y, z, n);
        g_pts[side][1][pair][pos] = make_float4(-2.0f * x, -2.0f * y, -2.0f * z, n);
    }
}

__global__ void prep_kernel(const float* __restrict__ rv,
                            const float* __restrict__ tgt) {
    const int pair = blockIdx.y;
    const int i = blockIdx.x * blockDim.x + threadIdx.x;   // 0..8191
    const int h = i / WW;
    const int w = i % WW;

    const float FOV_DOWN = -0.4363323129985824f;   // -25 deg
    const float FOV      = 0.4886921905584123f;    // 28 deg span
    const float PI_F     = 3.14159265358979323846f;

    float pitch = (1.0f - (h + 0.5f) / (float)HH) * FOV + FOV_DOWN;
    float yaw   = -(((w + 0.5f) / (float)WW) * 2.0f - 1.0f) * PI_F;
    float cp = cosf(pitch), sp = sinf(pitch);
    float cy = cosf(yaw),  sy = sinf(yaw);

    float r = rv[pair * HW + i];
    compact_push(0, pair, r > 0.0f, r * cp * cy, r * cp * sy, r * sp);

    const float* tp = tgt + (size_t)pair * 4 * HW + i;
    float t0 = tp[0];
    compact_push(1, pair, t0 > 0.0f, tp[HW], tp[2 * HW], tp[3 * HW]);
}

// ---------- NN + fused finalize ----------
__global__ void __launch_bounds__(NT) nn_kernel(float* __restrict__ out) {
    const int dir  = blockIdx.z;        // 0: queries = rv pts; 1: queries = target pts
    const int pair = blockIdx.y;
    const int nq = g_cnt[dir][pair];
    const int nt = g_cnt[1 - dir][pair];

    const float4* __restrict__ q  = g_pts[dir][0][pair];
    const float4* __restrict__ tg = g_pts[1 - dir][1][pair];

    // pair-packed SoA tile: sP[g] = (x0,x1,y0,y1), sQ[g] = (z0,z1,w0,w1)
    __shared__ float4 sP[NGRP];
    __shared__ float4 sQ[NGRP];
    __shared__ float  wsum[NT / 32];

    const int tid = threadIdx.x;
    float total = 0.0f;

    for (int qbase = blockIdx.x * QBLK; qbase < nq; qbase += GX * QBLK) {
        float4 qr[QPT];
        bool   qv[QPT];
        unsigned long long qx2[QPT], qy2[QPT], qz2[QPT];
#pragma unroll
        for (int k = 0; k < QPT; k++) {
            int idx = qbase + k * NT + tid;
            qv[k] = idx < nq;
            qr[k] = qv[k] ? q[idx] : make_float4(0.f, 0.f, 0.f, 0.f);
            qx2[k] = splat2(qr[k].x);
            qy2[k] = splat2(qr[k].y);
            qz2[k] = splat2(qr[k].z);
        }
        float mn[QPT][2];
#pragma unroll
        for (int k = 0; k < QPT; k++) { mn[k][0] = 3e38f; mn[k][1] = 3e38f; }

        for (int j0 = 0; j0 < nt; j0 += TILE) {
            __syncthreads();
            {   // thread tid packs targets (j0+2*tid, j0+2*tid+1)
                int ja = j0 + 2 * tid;
                float4 t0 = (ja     < nt) ? tg[ja]     : make_float4(0.f, 0.f, 0.f, 3e38f);
                float4 t1 = (ja + 1 < nt) ? tg[ja + 1] : make_float4(0.f, 0.f, 0.f, 3e38f);
                sP[tid] = make_float4(t0.x, t1.x, t0.y, t1.y);
                sQ[tid] = make_float4(t0.z, t1.z, t0.w, t1.w);
            }
            __syncthreads();

            const ulonglong2* __restrict__ pP = reinterpret_cast<const ulonglong2*>(sP);
            const ulonglong2* __restrict__ pQ = reinterpret_cast<const ulonglong2*>(sQ);
#pragma unroll 4
            for (int g = 0; g < NGRP; g++) {
                ulonglong2 P = pP[g];   // P.x = xpair, P.y = ypair
                ulonglong2 Q = pQ[g];   // Q.x = zpair, Q.y = wpair
#pragma unroll
                for (int k = 0; k < QPT; k++) {
                    // v = ||t||^2 - 2 q.t  (query norm added after the min)
                    unsigned long long v = fma2(qx2[k], P.x,
                                           fma2(qy2[k], P.y,
                                           fma2(qz2[k], Q.x, Q.y)));
                    float2 vf = unpack2(v);
                    mn[k][0] = fminf(mn[k][0], vf.x);
                    mn[k][1] = fminf(mn[k][1], vf.y);
                }
            }
        }
#pragma unroll
        for (int k = 0; k < QPT; k++)
            if (qv[k]) total += qr[k].w + fminf(mn[k][0], mn[k][1]);
    }

    // block reduction
#pragma unroll
    for (int o = 16; o; o >>= 1) total += __shfl_down_sync(0xffffffffu, total, o);
    if ((tid & 31) == 0) wsum[tid >> 5] = total;
    __syncthreads();
    if (tid == 0) {
        float s = 0.0f;
#pragma unroll
        for (int wi = 0; wi < NT / 32; wi++) s += wsum[wi];
        atomicAdd(&g_sum[dir][pair], s);

        __threadfence();
        int old = atomicAdd(&g_done, 1);
        if (old == GX * NPAIR * 2 - 1) {
            __threadfence();
            // finalize
            float cham[NPAIR];
#pragma unroll
            for (int p = 0; p < NPAIR; p++) {
                float c0 = (float)g_cnt[0][p]; if (c0 < 1.0f) c0 = 1.0f;
                float c1 = (float)g_cnt[1][p]; if (c1 < 1.0f) c1 = 1.0f;
                cham[p] = g_sum[0][p] / c0 + g_sum[1][p] / c1;
            }
            // tensor[s][b] = cham[b*SDIM + s]; per_step[s] = mean over b
#pragma unroll
            for (int s2 = 0; s2 < SDIM; s2++) {
                float acc = 0.0f;
#pragma unroll
                for (int b = 0; b < BDIM; b++) {
                    float c = cham[b * SDIM + s2];
                    out[SDIM + s2 * BDIM + b] = c;
                    acc += c;
                }
                out[s2] = acc / (float)BDIM;
            }
            // restore the zero-state invariant for the next call
#pragma unroll
            for (int p = 0; p < NPAIR; p++) {
                g_cnt[0][p] = 0; g_cnt[1][p] = 0;
                g_sum[0][p] = 0.0f; g_sum[1][p] = 0.0f;
            }
            g_done = 0;
        }
    }
}

extern "C" void kernel_launch(void* const* d_in, const int* in_sizes, int n_in,
                              void* d_out, int out_size) {
    const float* rv  = (const float*)d_in[0];
    const float* tgt = (const float*)d_in[1];
    // d_in[2] (mos_label) and d_in[3] (n_samples) are unused per the reference.

    prep_kernel<<<dim3(HW / 256, NPAIR), 256>>>(rv, tgt);
    nn_kernel<<<dim3(GX, NPAIR, 2), NT>>>((float*)d_out);
}

// round 4
// speedup vs baseline: 1.5423x; 1.0640x over previous
#include <cuda_runtime.h>
#include <cuda_bf16.h>

// Problem shape (fixed by the dataset)
#define HH 64
#define WW 128
#define HW (HH * WW)     // 8192 points per image
#define NPAIR 8          // B*S = 2*4
#define SDIM 4
#define BDIM 2

#define GX   9           // query chunks per (pair,dir)
#define NT   256         // threads per NN block
#define QPT  2           // queries per thread
#define QBLK (NT * QPT)  // 512 queries per block
#define TS   2           // target-dimension split (occupancy: 9*8*4 = 288 CTAs)
#define TILE 512         // targets per smem tile
#define NGRP (TILE / 2)  // packed target-pair groups per tile

#define FLT_MAX_BITS 0x7F7FFFFF

// Scratch (device globals; zero-state restored by the finalizer each call).
// g_pts[side][variant][pair][idx]: side 0 = rv back-projection, side 1 = target
// variant 0 = (x, y, z, ||p||^2)        -- queries
// variant 1 = (-2x, -2y, -2z, ||p||^2)  -- NN targets (-2 folded into FMAs)
__device__ float4 g_pts[2][2][NPAIR][HW];
__device__ int    g_min[2][NPAIR][HW];   // per-query NN dist (float bits), atomicMin-combined
__device__ int    g_cnt[2][NPAIR];
__device__ float  g_sum[2][NPAIR];
__device__ int    g_done;

// ---------- packed f32x2 helpers ----------
__device__ __forceinline__ unsigned long long splat2(float v) {
    unsigned long long r;
    asm("mov.b64 %0, {%1, %1};" : "=l"(r) : "f"(v));
    return r;
}
__device__ __forceinline__ unsigned long long fma2(unsigned long long a,
                                                   unsigned long long b,
                                                   unsigned long long c) {
    unsigned long long d;
    asm("fma.rn.f32x2 %0, %1, %2, %3;" : "=l"(d) : "l"(a), "l"(b), "l"(c));
    return d;
}
__device__ __forceinline__ float2 unpack2(unsigned long long v) {
    float2 r;
    asm("mov.b64 {%0, %1}, %2;" : "=f"(r.x), "=f"(r.y) : "l"(v));
    return r;
}

// ---------- prep: back-project + warp-aggregated stream compaction ----------
__device__ __forceinline__ void compact_push(int side, int pair, bool valid,
                                             float x, float y, float z) {
    unsigned m = __ballot_sync(0xffffffffu, valid);
    int lane = threadIdx.x & 31;
    int leader = __ffs(m) - 1;
    int cnt = __popc(m);
    int base = 0;
    if (cnt > 0) {
        if (lane == leader) base = atomicAdd(&g_cnt[side][pair], cnt);
        base = __shfl_sync(0xffffffffu, base, leader);
    }
    if (valid) {
        int pos = base + __popc(m & ((1u << lane) - 1u));
        float n = x * x + y * y + z * z;
        g_pts[side][0][pair][pos] = make_float4(x, y, z, n);
        g_pts[side][1][pair][pos] = make_float4(-2.0f * x, -2.0f * y, -2.0f * z, n);
    }
}

__global__ void prep_kernel(const float* __restrict__ rv,
                            const float* __restrict__ tgt) {
    const int pair = blockIdx.y;
    const int i = blockIdx.x * blockDim.x + threadIdx.x;   // 0..8191
    const int h = i / WW;
    const int w = i % WW;

    // init the per-query min buffers for this call
    g_min[0][pair][i] = FLT_MAX_BITS;
    g_min[1][pair][i] = FLT_MAX_BITS;

    const float FOV_DOWN = -0.4363323129985824f;   // -25 deg
    const float FOV      = 0.4886921905584123f;    // 28 deg span
    const float PI_F     = 3.14159265358979323846f;

    float pitch = (1.0f - (h + 0.5f) / (float)HH) * FOV + FOV_DOWN;
    float yaw   = -(((w + 0.5f) / (float)WW) * 2.0f - 1.0f) * PI_F;
    float cp = cosf(pitch), sp = sinf(pitch);
    float cy = cosf(yaw),  sy = sinf(yaw);

    float r = rv[pair * HW + i];
    compact_push(0, pair, r > 0.0f, r * cp * cy, r * cp * sy, r * sp);

    const float* tp = tgt + (size_t)pair * 4 * HW + i;
    float t0 = tp[0];
    compact_push(1, pair, t0 > 0.0f, tp[HW], tp[2 * HW], tp[3 * HW]);
}

// ---------- NN: each block = (query chunk) x (target half) ----------
__global__ void __launch_bounds__(NT) nn_kernel() {
    const int dir  = blockIdx.z >> 1;        // 0: queries = rv pts; 1: queries = target pts
    const int th   = blockIdx.z & 1;         // target half
    const int pair = blockIdx.y;
    const int nq = g_cnt[dir][pair];
    const int nt_all = g_cnt[1 - dir][pair];
    const int half = (nt_all + 1) >> 1;
    const int t_lo = th * half;
    const int t_hi = min(nt_all, t_lo + half);

    const float4* __restrict__ q  = g_pts[dir][0][pair];
    const float4* __restrict__ tg = g_pts[1 - dir][1][pair];

    // pair-packed SoA tile: sP[g] = (x0,x1,y0,y1), sQ[g] = (z0,z1,w0,w1)
    __shared__ float4 sP[NGRP];
    __shared__ float4 sQ[NGRP];

    const int tid = threadIdx.x;

    for (int qbase = blockIdx.x * QBLK; qbase < nq; qbase += GX * QBLK) {
        float4 qr[QPT];
        bool   qv[QPT];
        unsigned long long qx2[QPT], qy2[QPT], qz2[QPT];
#pragma unroll
        for (int k = 0; k < QPT; k++) {
            int idx = qbase + k * NT + tid;
            qv[k] = idx < nq;
            qr[k] = qv[k] ? q[idx] : make_float4(0.f, 0.f, 0.f, 0.f);
            qx2[k] = splat2(qr[k].x);
            qy2[k] = splat2(qr[k].y);
            qz2[k] = splat2(qr[k].z);
        }
        float mn[QPT][2];
#pragma unroll
        for (int k = 0; k < QPT; k++) { mn[k][0] = 3e38f; mn[k][1] = 3e38f; }

        for (int j0 = t_lo; j0 < t_hi; j0 += TILE) {
            __syncthreads();
            {   // thread tid packs targets (j0+2*tid, j0+2*tid+1)
                int ja = j0 + 2 * tid;
                float4 t0 = (ja     < t_hi) ? tg[ja]     : make_float4(0.f, 0.f, 0.f, 3e38f);
                float4 t1 = (ja + 1 < t_hi) ? tg[ja + 1] : make_float4(0.f, 0.f, 0.f, 3e38f);
                sP[tid] = make_float4(t0.x, t1.x, t0.y, t1.y);
                sQ[tid] = make_float4(t0.z, t1.z, t0.w, t1.w);
            }
            __syncthreads();

            const ulonglong2* __restrict__ pP = reinterpret_cast<const ulonglong2*>(sP);
            const ulonglong2* __restrict__ pQ = reinterpret_cast<const ulonglong2*>(sQ);
#pragma unroll 4
            for (int g = 0; g < NGRP; g++) {
                ulonglong2 P = pP[g];   // P.x = xpair, P.y = ypair
                ulonglong2 Q = pQ[g];   // Q.x = zpair, Q.y = wpair
#pragma unroll
                for (int k = 0; k < QPT; k++) {
                    // v = ||t||^2 - 2 q.t  (query norm added after the min)
                    unsigned long long v = fma2(qx2[k], P.x,
                                           fma2(qy2[k], P.y,
                                           fma2(qz2[k], Q.x, Q.y)));
                    float2 vf = unpack2(v);
                    mn[k][0] = fminf(mn[k][0], vf.x);
                    mn[k][1] = fminf(mn[k][1], vf.y);
                }
            }
        }
#pragma unroll
        for (int k = 0; k < QPT; k++) {
            if (qv[k]) {
                float d = qr[k].w + fminf(mn[k][0], mn[k][1]);   // >= -eps
                int idx = qbase + k * NT + tid;
                atomicMin(&g_min[dir][pair][idx], __float_as_int(d));
            }
        }
    }
}

// ---------- sum per (pair,dir) + fused finalize ----------
#define NTS 256
__global__ void sum_kernel(float* __restrict__ out) {
    const int pair = blockIdx.x >> 1;
    const int dir  = blockIdx.x & 1;
    const int nq = g_cnt[dir][pair];
    const int tid = threadIdx.x;

    float s = 0.0f;
    for (int i = tid; i < nq; i += NTS)
        s += __int_as_float(g_min[dir][pair][i]);

#pragma unroll
    for (int o = 16; o; o >>= 1) s += __shfl_down_sync(0xffffffffu, s, o);
    __shared__ float wsum[NTS / 32];
    if ((tid & 31) == 0) wsum[tid >> 5] = s;
    __syncthreads();
    if (tid == 0) {
        float t = 0.0f;
#pragma unroll
        for (int wi = 0; wi < NTS / 32; wi++) t += wsum[wi];
        float c = (float)nq; if (c < 1.0f) c = 1.0f;
        g_sum[dir][pair] = t / c;

        __threadfence();
        int old = atomicAdd(&g_done, 1);
        if (old == NPAIR * 2 - 1) {
            __threadfence();
            float cham[NPAIR];
#pragma unroll
            for (int p = 0; p < NPAIR; p++)
                cham[p] = g_sum[0][p] + g_sum[1][p];
            // tensor[s][b] = cham[b*SDIM + s]; per_step[s] = mean over b
#pragma unroll
            for (int s2 = 0; s2 < SDIM; s2++) {
                float acc = 0.0f;
#pragma unroll
                for (int b = 0; b < BDIM; b++) {
                    float cv = cham[b * SDIM + s2];
                    out[SDIM + s2 * BDIM + b] = cv;
                    acc += cv;
                }
                out[s2] = acc / (float)BDIM;
            }
            // restore zero-state invariant for the next call
#pragma unroll
            for (int p = 0; p < NPAIR; p++) { g_cnt[0][p] = 0; g_cnt[1][p] = 0; }
            g_done = 0;
        }
    }
}

extern "C" void kernel_launch(void* const* d_in, const int* in_sizes, int n_in,
                              void* d_out, int out_size) {
    const float* rv  = (const float*)d_in[0];
    const float* tgt = (const float*)d_in[1];
    // d_in[2] (mos_label) and d_in[3] (n_samples) are unused per the reference.

    prep_kernel<<<dim3(HW / 256, NPAIR), 256>>>(rv, tgt);
    nn_kernel<<<dim3(GX, NPAIR, 2 * TS), NT>>>();
    sum_kernel<<<NPAIR * 2, NTS>>>((float*)d_out);
}